// round 3
// baseline (speedup 1.0000x reference)
#include <cuda_runtime.h>

// Windowed local attention, k=7, H=W=256, C=32, fp32.
// Tile: 32x4 pixels, 128 threads. Halo staged in 16-channel chunks
// (23.8KB smem) -> 6 blocks/SM, 24 warps. Pass2 stores per-chunk direct.

#define H_IMG 256
#define W_IMG 256
#define C 32
#define NC 16              // channels per staged chunk
#define K 7
#define PAD 3
#define TX 32
#define TY 4
#define HW 38              // TX + K - 1
#define HH 10              // TY + K - 1
#define CS 381             // HW*HH = 380, +1 pad
#define NTHREADS 128
#define SMEM_BYTES (NC * CS * 4)

// Stage NC channels [chunk*NC, chunk*NC+NC) of src's halo into smem,
// channel-major, zero-padded OOB.
__device__ __forceinline__ void stage_halo16(float* __restrict__ buf,
                                             const float* __restrict__ src,
                                             int bx, int by, int tid, int chunk) {
    for (int idx = tid; idx < HW * HH * (NC / 4); idx += NTHREADS) {
        int cg = idx & 3;                 // channel group within chunk (4 ch each)
        int wp = (idx >> 2) % HW;
        int hp = (idx >> 2) / HW;
        int gw = bx * TX - PAD + wp;
        int gh = by * TY - PAD + hp;
        float4 r = make_float4(0.f, 0.f, 0.f, 0.f);
        if (gw >= 0 && gw < W_IMG && gh >= 0 && gh < H_IMG) {
            r = *reinterpret_cast<const float4*>(
                src + ((gh << 8) + gw) * C + chunk * NC + (cg << 2));
        }
        int s = hp * HW + wp;
        int c0 = cg << 2;
        buf[(c0 + 0) * CS + s] = r.x;
        buf[(c0 + 1) * CS + s] = r.y;
        buf[(c0 + 2) * CS + s] = r.z;
        buf[(c0 + 3) * CS + s] = r.w;
    }
}

__global__ __launch_bounds__(NTHREADS, 6)
void local_attn_kernel(const float* __restrict__ main_in,
                       const float* __restrict__ ref_in,
                       const float* __restrict__ val_in,
                       float* __restrict__ out) {
    extern __shared__ float smem[];
    float* buf = smem;               // [NC][CS]

    const int tid = threadIdx.x;
    const int bx = blockIdx.x, by = blockIdx.y;
    const int px = tid & 31;         // lane
    const int py = tid >> 5;         // warp id = row in tile

    const int gpix = (((by * TY + py) << 8) + bx * TX + px) * C;

    float sc[K * K];
    #pragma unroll
    for (int p = 0; p < K * K; p++) sc[p] = 0.f;

    // ---- Pass 1: scores, two 16-channel chunks ----
    #pragma unroll
    for (int chunk = 0; chunk < 2; chunk++) {
        if (chunk) __syncthreads();            // prior reads done before restage
        stage_halo16(buf, ref_in, bx, by, tid, chunk);

        float m[NC];
        #pragma unroll
        for (int i = 0; i < NC / 4; i++) {
            float4 t = *reinterpret_cast<const float4*>(
                main_in + gpix + chunk * NC + 4 * i);
            m[4 * i + 0] = t.x;
            m[4 * i + 1] = t.y;
            m[4 * i + 2] = t.z;
            m[4 * i + 3] = t.w;
        }
        __syncthreads();

        const float* rbase = buf + py * HW + px;
        #pragma unroll
        for (int c = 0; c < NC; c++) {
            float mc = m[c];
            #pragma unroll
            for (int dh = 0; dh < K; dh++) {
                #pragma unroll
                for (int dw = 0; dw < K; dw++) {
                    sc[dh * K + dw] =
                        fmaf(rbase[c * CS + dh * HW + dw], mc, sc[dh * K + dw]);
                }
            }
        }
    }

    // ---- Softmax over 49 positions (OOB positions carry score 0, included) ----
    float mx = sc[0];
    #pragma unroll
    for (int p = 1; p < K * K; p++) mx = fmaxf(mx, sc[p]);
    float sum = 0.f;
    #pragma unroll
    for (int p = 0; p < K * K; p++) {
        sc[p] = __expf(sc[p] - mx);
        sum += sc[p];
    }
    float inv = 1.f / sum;
    #pragma unroll
    for (int p = 0; p < K * K; p++) sc[p] *= inv;

    // ---- Pass 2: output, two 16-channel chunks, direct store ----
    #pragma unroll
    for (int chunk = 0; chunk < 2; chunk++) {
        __syncthreads();                       // prior reads done before restage
        stage_halo16(buf, val_in, bx, by, tid, chunk);
        __syncthreads();

        const float* vbase = buf + py * HW + px;
        float acc[NC];
        #pragma unroll
        for (int c = 0; c < NC; c++) {
            float a = 0.f;
            #pragma unroll
            for (int dh = 0; dh < K; dh++) {
                #pragma unroll
                for (int dw = 0; dw < K; dw++) {
                    a = fmaf(sc[dh * K + dw], vbase[c * CS + dh * HW + dw], a);
                }
            }
            acc[c] = a;
        }

        float* o = out + gpix + chunk * NC;
        #pragma unroll
        for (int i = 0; i < NC / 4; i++) {
            *reinterpret_cast<float4*>(o + 4 * i) =
                make_float4(acc[4 * i], acc[4 * i + 1], acc[4 * i + 2], acc[4 * i + 3]);
        }
    }
}

extern "C" void kernel_launch(void* const* d_in, const int* in_sizes, int n_in,
                              void* d_out, int out_size) {
    const float* main_in = (const float*)d_in[0];
    const float* ref_in  = (const float*)d_in[1];
    const float* val_in  = (const float*)d_in[2];
    float* out = (float*)d_out;

    cudaFuncSetAttribute(local_attn_kernel,
                         cudaFuncAttributeMaxDynamicSharedMemorySize, SMEM_BYTES);

    dim3 grid(W_IMG / TX, H_IMG / TY);
    local_attn_kernel<<<grid, NTHREADS, SMEM_BYTES>>>(main_in, ref_in, val_in, out);
}

// round 4
// speedup vs baseline: 1.0241x; 1.0241x over previous
#include <cuda_runtime.h>

// Windowed local attention, k=7, H=W=256, C=32, fp32.
// 256 threads / 32x4-pixel tile: TWO threads per pixel (16 channels each),
// partial scores combined via shfl_xor(16). Full 32-ch halo buffer 48.8KB.

#define H_IMG 256
#define W_IMG 256
#define C 32
#define HC 16              // channels per thread (half)
#define K 7
#define PAD 3
#define TX 32
#define TY 4
#define HW 38              // TX + K - 1
#define HH 10              // TY + K - 1
#define CS 381             // HW*HH = 380, +1 pad (odd)
#define NTHREADS 256
#define SMEM_BYTES (C * CS * 4)

// Stage all 32 channels of src's halo into smem, channel-major, zero-pad OOB.
__device__ __forceinline__ void stage_halo(float* __restrict__ buf,
                                           const float* __restrict__ src,
                                           int bx, int by, int tid) {
    for (int idx = tid; idx < HW * HH * (C / 4); idx += NTHREADS) {
        int cg = idx & 7;                 // channel group (4 ch each)
        int wp = (idx >> 3) % HW;
        int hp = (idx >> 3) / HW;
        int gw = bx * TX - PAD + wp;
        int gh = by * TY - PAD + hp;
        float4 r = make_float4(0.f, 0.f, 0.f, 0.f);
        if (gw >= 0 && gw < W_IMG && gh >= 0 && gh < H_IMG) {
            r = *reinterpret_cast<const float4*>(src + ((gh << 8) + gw) * C + (cg << 2));
        }
        int s = hp * HW + wp;
        int c0 = cg << 2;
        buf[(c0 + 0) * CS + s] = r.x;
        buf[(c0 + 1) * CS + s] = r.y;
        buf[(c0 + 2) * CS + s] = r.z;
        buf[(c0 + 3) * CS + s] = r.w;
    }
}

__global__ __launch_bounds__(NTHREADS, 3)
void local_attn_kernel(const float* __restrict__ main_in,
                       const float* __restrict__ ref_in,
                       const float* __restrict__ val_in,
                       float* __restrict__ out) {
    extern __shared__ float smem[];
    float* buf = smem;               // [C][CS]

    const int tid = threadIdx.x;
    const int bx = blockIdx.x, by = blockIdx.y;
    const int wid = tid >> 5;        // 0..7
    const int lane = tid & 31;
    const int py = wid >> 1;                       // tile row 0..3
    const int px = ((wid & 1) << 4) + (lane & 15); // tile col 0..31
    const int half = lane >> 4;                    // channel half 0/1
    const int c0 = half * HC;

    const int gpix = (((by * TY + py) << 8) + bx * TX + px) * C;

    // ---- Stage ref halo (all 32 channels) ----
    stage_halo(buf, ref_in, bx, by, tid);

    // ---- Load this thread's 16 query channels ----
    float m[HC];
    #pragma unroll
    for (int i = 0; i < HC / 4; i++) {
        float4 t = *reinterpret_cast<const float4*>(main_in + gpix + c0 + 4 * i);
        m[4 * i + 0] = t.x;
        m[4 * i + 1] = t.y;
        m[4 * i + 2] = t.z;
        m[4 * i + 3] = t.w;
    }

    __syncthreads();

    // ---- Pass 1: partial scores over this thread's 16 channels ----
    float sc[K * K];
    #pragma unroll
    for (int p = 0; p < K * K; p++) sc[p] = 0.f;

    const float* rbase = buf + c0 * CS + py * HW + px;
    #pragma unroll
    for (int c = 0; c < HC; c++) {
        float mc = m[c];
        #pragma unroll
        for (int dh = 0; dh < K; dh++) {
            #pragma unroll
            for (int dw = 0; dw < K; dw++) {
                sc[dh * K + dw] =
                    fmaf(rbase[c * CS + dh * HW + dw], mc, sc[dh * K + dw]);
            }
        }
    }

    // ---- Combine halves: full score in both partner lanes ----
    #pragma unroll
    for (int p = 0; p < K * K; p++)
        sc[p] += __shfl_xor_sync(0xffffffffu, sc[p], 16);

    // ---- Softmax over 49 positions (OOB positions carry score 0, included) ----
    float mx = sc[0];
    #pragma unroll
    for (int p = 1; p < K * K; p++) mx = fmaxf(mx, sc[p]);
    float sum = 0.f;
    #pragma unroll
    for (int p = 0; p < K * K; p++) {
        sc[p] = __expf(sc[p] - mx);
        sum += sc[p];
    }
    float inv = 1.f / sum;
    #pragma unroll
    for (int p = 0; p < K * K; p++) sc[p] *= inv;

    // ---- Stage val halo (overwrite buffer) ----
    __syncthreads();                 // all pass-1 reads done
    stage_halo(buf, val_in, bx, by, tid);
    __syncthreads();

    // ---- Pass 2: this thread's 16 output channels, direct coalesced store ----
    const float* vbase = buf + c0 * CS + py * HW + px;
    float acc[HC];
    #pragma unroll
    for (int c = 0; c < HC; c++) {
        float a = 0.f;
        #pragma unroll
        for (int dh = 0; dh < K; dh++) {
            #pragma unroll
            for (int dw = 0; dw < K; dw++) {
                a = fmaf(sc[dh * K + dw], vbase[c * CS + dh * HW + dw], a);
            }
        }
        acc[c] = a;
    }

    float* o = out + gpix + c0;
    #pragma unroll
    for (int i = 0; i < HC / 4; i++) {
        *reinterpret_cast<float4*>(o + 4 * i) =
            make_float4(acc[4 * i], acc[4 * i + 1], acc[4 * i + 2], acc[4 * i + 3]);
    }
}

extern "C" void kernel_launch(void* const* d_in, const int* in_sizes, int n_in,
                              void* d_out, int out_size) {
    const float* main_in = (const float*)d_in[0];
    const float* ref_in  = (const float*)d_in[1];
    const float* val_in  = (const float*)d_in[2];
    float* out = (float*)d_out;

    cudaFuncSetAttribute(local_attn_kernel,
                         cudaFuncAttributeMaxDynamicSharedMemorySize, SMEM_BYTES);

    dim3 grid(W_IMG / TX, H_IMG / TY);
    local_attn_kernel<<<grid, NTHREADS, SMEM_BYTES>>>(main_in, ref_in, val_in, out);
}